// round 12
// baseline (speedup 1.0000x reference)
#include <cuda_runtime.h>
#include <cstdint>
#include <cstddef>

// Fixed shapes
#define Nn 4
#define Cc 32
#define SIN 262144                        // 64^3
#define SOUT 32768                        // 32^3
#define NPOINTS 131072
#define GI_ELEMS ((size_t)Nn * Cc * SIN)
#define GG_ELEMS (NPOINTS * 3)
#define NROWS (Nn * 64 * 64)              // 16384 row bins (n, z0, y0)
#define RCAP 64
#define NBLK (Nn * 64 * 32)               // 8192 row-pair blocks

#define TP_BLOCKS 4096                    // gout transpose tiles (1024 x 4n)
#define ZR_BLOCKS 1600                    // zero rowcnt + gGrid

// Static device scratch
__device__ float  g_gout_t[(size_t)NPOINTS * Cc];     // gOut channels-last [p][c] (16MB)
__device__ int    g_rowcnt[NROWS];
__device__ float4 g_recs[(size_t)NROWS * RCAP];       // {tx,ty,tz, bits(p | x0<<20)}

// ---------------- prep: gout transpose + zero rowcnt/gGrid ----------------
__global__ void __launch_bounds__(256) k_prep(const float* __restrict__ gOut,
                                              float* __restrict__ gGrid) {
    const int bx = blockIdx.x, t = threadIdx.x;
    if (bx < TP_BLOCKS) {
        __shared__ float tile[32][33];
        const int n = bx >> 10;
        const int s0 = (bx & 1023) * 32;
        {
            const int c = t >> 3, s4 = t & 7;
            const float4 v = __ldg((const float4*)(gOut + ((size_t)n * Cc + c) * SOUT + s0) + s4);
            tile[c][s4 * 4 + 0] = v.x; tile[c][s4 * 4 + 1] = v.y;
            tile[c][s4 * 4 + 2] = v.z; tile[c][s4 * 4 + 3] = v.w;
        }
        __syncthreads();
        {
            const int s = t >> 3, cq = t & 7;
            float4 w;
            w.x = tile[cq * 4 + 0][s]; w.y = tile[cq * 4 + 1][s];
            w.z = tile[cq * 4 + 2][s]; w.w = tile[cq * 4 + 3][s];
            ((float4*)(g_gout_t + ((size_t)n * SOUT + s0 + s) * Cc))[cq] = w;
        }
    } else {
        const int i = (bx - TP_BLOCKS) * 256 + t;
        if (i < NROWS) g_rowcnt[i] = 0;
        if (i < GG_ELEMS) gGrid[i] = 0.f;
    }
}

// ---------------- bin points by (n, z0, y0) row ----------------
__global__ void __launch_bounds__(256) k_bin(const float* __restrict__ grid) {
    const int p = blockIdx.x * 256 + threadIdx.x;
    const float gx = __ldg(grid + (size_t)p * 3 + 0);
    const float gy = __ldg(grid + (size_t)p * 3 + 1);
    const float gz = __ldg(grid + (size_t)p * 3 + 2);
    const float ix = (gx + 1.f) * 31.5f;
    const float iy = (gy + 1.f) * 31.5f;
    const float iz = (gz + 1.f) * 31.5f;
    const float fx = floorf(ix), fy = floorf(iy), fz = floorf(iz);
    const float tx = ix - fx, ty = iy - fy, tz = iz - fz;
    const int x0 = min(max((int)fx, 0), 63);
    const int y0 = min(max((int)fy, 0), 63);
    const int z0 = min(max((int)fz, 0), 63);
    const int n = p >> 15;
    const int bin = (n * 64 + z0) * 64 + y0;
    const int pos = atomicAdd(&g_rowcnt[bin], 1);
    if (pos < RCAP)
        g_recs[(size_t)bin * RCAP + pos] =
            make_float4(tx, ty, tz, __int_as_float(p | (x0 << 20)));
}

// ---------------- unified row-pair kernel: grad_input + grad_grid ----------------
// One block per (n, z, yp): owns rows y=2yp and y=2yp+1 at depth z.
// Bins visited: z0 in {z-1, z} x y0 in {2yp-1, 2yp, 2yp+1} = 6 bins.
__global__ void __launch_bounds__(256) k_row(const float* __restrict__ inp,
                                             float* __restrict__ gInp,
                                             float* __restrict__ gGrid) {
    __shared__ float  s_inp[2][65][33];   // x=64 zero pad
    __shared__ float  s_acc[2][65][33];   // x=64 dummy sink
    __shared__ float4 s_recs[6][RCAP];
    __shared__ int    s_cnt[6];

    const int t = threadIdx.x;
    const int wid = t >> 5, lane = t & 31;
    const int n  = blockIdx.x >> 11;
    const int z  = (blockIdx.x >> 5) & 63;
    const int yp = blockIdx.x & 31;

    // Load 2 input rows: 4 x LDG.128 per thread
#pragma unroll
    for (int j = 0; j < 4; j++) {
        const int u = j * 256 + t;                 // 0..1023
        const int r = u >> 9, c = (u >> 4) & 31, xq = u & 15;
        const float4 v = __ldcs((const float4*)(inp + ((size_t)(n * Cc + c)) * SIN
                                                + (size_t)z * 4096 + (2 * yp + r) * 64) + xq);
        s_inp[r][xq * 4 + 0][c] = v.x; s_inp[r][xq * 4 + 1][c] = v.y;
        s_inp[r][xq * 4 + 2][c] = v.z; s_inp[r][xq * 4 + 3][c] = v.w;
    }
    // Zero accumulators (incl. pad) + input pad columns
    {
        float* pa = &s_acc[0][0][0];
        for (int i = t; i < 2 * 65 * 33; i += 256) pa[i] = 0.f;
        if (t < 66) {
            const int r = (t >= 33) ? 1 : 0;
            s_inp[r][64][t - (r ? 33 : 0)] = 0.f;
        }
    }

    // Warps 0..5 load the 6 neighbor bins: wid -> (zi, yi); z0 = z-1+zi, y0 = 2yp-1+yi
    if (wid < 6) {
        const int zi = (wid >= 3) ? 1 : 0;
        const int yi = wid - (zi ? 3 : 0);
        const int z0 = z - 1 + zi;
        const int y0 = 2 * yp - 1 + yi;
        int cnt = 0;
        if (((unsigned)z0 < 64u) & ((unsigned)y0 < 64u)) {
            const int bin = (n * 64 + z0) * 64 + y0;
            cnt = min(g_rowcnt[bin], RCAP);
            for (int e = lane; e < cnt; e += 32)
                s_recs[wid][e] = g_recs[(size_t)bin * RCAP + e];
        }
        if (lane == 0) s_cnt[wid] = cnt;
    }
    __syncthreads();

    const bool lo16 = lane < 16;

#pragma unroll
    for (int bi = 0; bi < 6; bi++) {
        const int cnt = s_cnt[bi];
        const bool ziHi = (bi >= 3);              // z0 = z  (dz=0)
        const int  yi   = bi - (ziHi ? 3 : 0);
        for (int e = wid; e < cnt; e += 8) {
            const float4 r = s_recs[bi][e];
            const int bits = __float_as_int(r.w);
            const int p  = bits & 0xFFFFF;
            const int x0 = bits >> 20;
            const float wz = ziHi ? (1.f - r.z) : r.z;   // dz=1 corner when z0=z-1
            const float sz = ziHi ? -1.f : 1.f;
            const float wxa = 1.f - r.x, wxb = r.x;

            const float go = g_gout_t[(size_t)p * 32 + lane];   // coalesced, L2-resident

            if (yi == 1) {
                // y0 = 2yp: both rows in-block. row0: dy=0, row1: dy=1.
                const float wy0 = 1.f - r.y, wy1 = r.y;
                const float w0 = wy0 * wz, w1 = wy1 * wz;
                atomicAdd(&s_acc[0][x0][lane],     wxa * w0 * go);
                atomicAdd(&s_acc[0][x0 + 1][lane], wxb * w0 * go);
                atomicAdd(&s_acc[1][x0][lane],     wxa * w1 * go);
                atomicAdd(&s_acc[1][x0 + 1][lane], wxb * w1 * go);
                const float Q0 = go * s_inp[0][x0][lane];
                const float Q1 = go * s_inp[0][x0 + 1][lane];
                const float Q2 = go * s_inp[1][x0][lane];
                const float Q3 = go * s_inp[1][x0 + 1][lane];
                // Quad reduction: 9 shuffles.
                float sA = lo16 ? Q1 : Q0;
                sA = __shfl_xor_sync(0xFFFFFFFFu, sA, 16);
                const float A = lo16 ? Q0 + sA : Q1 + sA;
                float sB = lo16 ? Q3 : Q2;
                sB = __shfl_xor_sync(0xFFFFFFFFu, sB, 16);
                const float B = lo16 ? Q2 + sB : Q3 + sB;
                const bool lo8 = (lane & 8) == 0;
                float sC = lo8 ? B : A;
                sC = __shfl_xor_sync(0xFFFFFFFFu, sC, 8);
                float C = lo8 ? A + sC : B + sC;
                C += __shfl_xor_sync(0xFFFFFFFFu, C, 4);
                C += __shfl_xor_sync(0xFFFFFFFFu, C, 2);
                C += __shfl_xor_sync(0xFFFFFFFFu, C, 1);
                // groups: 0-7 S(Q0)=Sa0, 8-15 S(Q2)=Sa1, 16-23 S(Q1)=Sb0, 24-31 S(Q3)=Sb1
                const float Sa0 = __shfl_sync(0xFFFFFFFFu, C, 0);
                const float Sa1 = __shfl_sync(0xFFFFFFFFu, C, 8);
                const float Sb0 = __shfl_sync(0xFFFFFFFFu, C, 16);
                const float Sb1 = __shfl_sync(0xFFFFFFFFu, C, 24);
                if (lane < 3) {
                    const float Qr0 = wxa * Sa0 + wxb * Sb0;
                    const float Qr1 = wxa * Sa1 + wxb * Sb1;
                    const float vx = wz * (wy0 * (Sb0 - Sa0) + wy1 * (Sb1 - Sa1)) * 31.5f;
                    const float vy = wz * (Qr1 - Qr0) * 31.5f;        // sy0=-1, sy1=+1
                    const float vz = sz * (wy0 * Qr0 + wy1 * Qr1) * 31.5f;
                    const float val = (lane == 0) ? vx : (lane == 1) ? vy : vz;
                    atomicAdd(gGrid + (size_t)p * 3 + lane, val);
                }
            } else {
                // Single row: yi=0 -> row0, dy=1 (wy=ty, sy=+1); yi=2 -> row1, dy=0.
                const int ra   = (yi == 0) ? 0 : 1;
                const float wy = (yi == 0) ? r.y : (1.f - r.y);
                const float sy = (yi == 0) ? 1.f : -1.f;
                const float wyz = wy * wz;
                atomicAdd(&s_acc[ra][x0][lane],     wxa * wyz * go);
                atomicAdd(&s_acc[ra][x0 + 1][lane], wxb * wyz * go);
                float Pa = go * s_inp[ra][x0][lane];
                float Pb = go * s_inp[ra][x0 + 1][lane];
                // Merged dual reduction: 6 shuffles.
                const float send = lo16 ? Pb : Pa;
                const float recv = __shfl_xor_sync(0xFFFFFFFFu, send, 16);
                float R = lo16 ? (Pa + recv) : (Pb + recv);
#pragma unroll
                for (int o = 8; o > 0; o >>= 1)
                    R += __shfl_xor_sync(0xFFFFFFFFu, R, o);
                const float other = __shfl_xor_sync(0xFFFFFFFFu, R, 16);
                if (lane < 3) {
                    const float PA = R, PB = other;   // lane<3 => lo16
                    const float Q = wxa * PA + wxb * PB;
                    const float vx = wyz * (PB - PA) * 31.5f;
                    const float vy = sy * wz * Q * 31.5f;
                    const float vz = sz * wy * Q * 31.5f;
                    const float val = (lane == 0) ? vx : (lane == 1) ? vy : vz;
                    atomicAdd(gGrid + (size_t)p * 3 + lane, val);
                }
            }
        }
    }
    __syncthreads();

    // Write 2 grad_input rows: 4 x STG.128 per thread
#pragma unroll
    for (int j = 0; j < 4; j++) {
        const int u = j * 256 + t;
        const int r = u >> 9, c = (u >> 4) & 31, xq = u & 15;
        float4 w;
        w.x = s_acc[r][xq * 4 + 0][c]; w.y = s_acc[r][xq * 4 + 1][c];
        w.z = s_acc[r][xq * 4 + 2][c]; w.w = s_acc[r][xq * 4 + 3][c];
        __stcs((float4*)(gInp + ((size_t)(n * Cc + c)) * SIN
                         + (size_t)z * 4096 + (2 * yp + r) * 64) + xq, w);
    }
}

extern "C" void kernel_launch(void* const* d_in, const int* in_sizes, int n_in,
                              void* d_out, int out_size) {
    const float* gOut = (const float*)d_in[0];  // [N,C,Do,Ho,Wo]
    const float* inp  = (const float*)d_in[1];  // [N,C,D,H,W]
    const float* grid = (const float*)d_in[2];  // [N,Do,Ho,Wo,3]
    float* out = (float*)d_out;

    float* gInp  = out;              // [N,C,D,H,W]
    float* gGrid = out + GI_ELEMS;   // [N,Do,Ho,Wo,3]

    // 1) prep: gout transpose + zero rowcnt/gGrid
    k_prep<<<TP_BLOCKS + ZR_BLOCKS, 256>>>(gOut, gGrid);
    // 2) bin points by cell row
    k_bin<<<NPOINTS / 256, 256>>>(grid);
    // 3) unified row-pair kernel
    k_row<<<NBLK, 256>>>(inp, gInp, gGrid);
}